// round 2
// baseline (speedup 1.0000x reference)
#include <cuda_runtime.h>
#include <math.h>

// Problem constants
#define Nn 32
#define Cc 64
#define Tt 300
#define Vv 25
#define Mm 2
#define Oo 64
#define Ss 3
#define SO 192          // S*O rows of conv_w
#define TTile 6         // T-tile per block (300 = 50*6)
#define TVC (TTile*Vv)  // 150 columns per tile
#define SXS 152         // padded stride for sx/sy (even -> 8B-aligned pairs)
#define SYS 152
#define SWS 193         // padded stride for transposed W
#define THREADS 480     // 15 warps; tasks per stage == 480 exactly

#define SM_FLOATS (Cc*SXS + SO*SYS + Cc*SWS + Ss*Vv*Vv + SO + Oo + Oo)

typedef unsigned long long ull;

__device__ __forceinline__ ull pack2(float lo, float hi) {
    ull r; asm("mov.b64 %0, {%1,%2};" : "=l"(r) : "f"(lo), "f"(hi)); return r;
}
__device__ __forceinline__ ull pack2s(float v) {
    ull r; asm("mov.b64 %0, {%1,%1};" : "=l"(r) : "f"(v)); return r;
}
__device__ __forceinline__ void fma2(ull& d, ull a, ull b) {
    asm("fma.rn.f32x2 %0, %1, %2, %0;" : "+l"(d) : "l"(a), "l"(b));
}
__device__ __forceinline__ float2 unpack2(ull v) {
    float2 f; asm("mov.b64 {%0,%1}, %2;" : "=f"(f.x), "=f"(f.y) : "l"(v)); return f;
}

__global__ __launch_bounds__(THREADS, 1)
void stgcn_fused_kernel(const float* __restrict__ x,
                        const float* __restrict__ PA,
                        const float* __restrict__ Wc,
                        const float* __restrict__ bc,
                        const float* __restrict__ gamma,
                        const float* __restrict__ beta,
                        const float* __restrict__ mean,
                        const float* __restrict__ var,
                        float* __restrict__ out)
{
    extern __shared__ float sm[];
    float* sx     = sm;                      // 64*152
    float* sy     = sx + Cc*SXS;             // 192*152
    float* sW     = sy + SO*SYS;             // 64*193
    float* sPA    = sW + Cc*SWS;             // 1875
    float* sbias  = sPA + Ss*Vv*Vv;          // 192
    float* sscale = sbias + SO;              // 64
    float* sshift = sscale + Oo;             // 64

    const int tid  = threadIdx.x;
    const int bid  = blockIdx.x;
    const int b    = bid & 63;               // batch index (n*2+m), fastest
    const int tile = bid >> 6;
    const int n    = b >> 1;
    const int m    = b & 1;
    const int t0   = tile * TTile;

    // ---- cooperative loads ----
    for (int i = tid; i < Ss*Vv*Vv; i += THREADS) sPA[i] = PA[i];
    for (int i = tid; i < SO; i += THREADS)       sbias[i] = bc[i];
    if (tid < Oo) {
        float sc = gamma[tid] * rsqrtf(var[tid] + 1e-5f);
        sscale[tid] = sc;
        sshift[tid] = beta[tid] - mean[tid] * sc;
    }
    // W transpose into smem: sW[c][so] = conv_w[so][c]
    for (int i = tid; i < SO*Cc; i += THREADS) {
        int so = i >> 6;
        int c  = i & 63;
        sW[c*SWS + so] = Wc[i];
    }
    // x tile: gather (stride-2 in global due to M-last layout)
    for (int i = tid; i < Cc*TVC; i += THREADS) {
        int c  = i / TVC;
        int tv = i - c*TVC;
        int t  = tv / Vv;
        int v  = tv - t*Vv;
        sx[c*SXS + tv] = x[ (((n*Cc + c)*Tt + (t0+t))*Vv + v)*Mm + m ];
    }
    __syncthreads();

    // ---- Stage A: conv GEMM  y[so][tv] = bias[so] + sum_c W[so][c]*x[c][tv]
    // 192x150 outputs, reg tile 6(so) x 10(tv as 5 f32x2 pairs); 32x15 = 480 tasks
    {
        const int sog = tid / 15;          // 0..31
        const int tvg = tid - sog*15;      // 0..14
        const int so0 = sog*6;
        const int tv0 = tvg*10;            // even -> 8B aligned pairs

        ull acc[6][5];
        #pragma unroll
        for (int i = 0; i < 6; i++) {
            ull bb = pack2s(sbias[so0+i]);
            #pragma unroll
            for (int j = 0; j < 5; j++) acc[i][j] = bb;
        }

        #pragma unroll 2
        for (int c = 0; c < Cc; c++) {
            const float* xrow = sx + c*SXS + tv0;
            ull xv[5];
            #pragma unroll
            for (int j = 0; j < 5; j++)
                xv[j] = *reinterpret_cast<const ull*>(xrow + 2*j);
            const float* wrow = sW + c*SWS + so0;
            #pragma unroll
            for (int i = 0; i < 6; i++) {
                ull wv = pack2s(wrow[i]);
                #pragma unroll
                for (int j = 0; j < 5; j++) fma2(acc[i][j], wv, xv[j]);
            }
        }

        #pragma unroll
        for (int i = 0; i < 6; i++) {
            float* yrow = sy + (so0+i)*SYS + tv0;
            #pragma unroll
            for (int j = 0; j < 5; j++)
                *reinterpret_cast<ull*>(yrow + 2*j) = acc[i][j];
        }
    }
    __syncthreads();

    // ---- Stage B: adjacency + BN + relu + residual + relu + store
    // z[o][t][w] = sum_s sum_v PA[s][v][w] * y[s*64+o][t*25+v]
    // reg tile 4(o as 2 f32x2 pairs) x 5(w); 16(og)*6(t)*5(wg) = 480 tasks
    {
        const int wg  = tid % 5;
        const int tq  = (tid/5) % 6;
        const int og  = tid / 30;          // 0..15
        const int o0  = og*4;
        const int w0  = wg*5;

        ull acc0[5], acc1[5];
        #pragma unroll
        for (int j = 0; j < 5; j++) { acc0[j] = 0ull; acc1[j] = 0ull; }

        #pragma unroll
        for (int s = 0; s < Ss; s++) {
            const float* pabase = sPA + s*(Vv*Vv) + w0;
            const float* yp     = sy + (s*Oo + o0)*SYS + tq*Vv;
            #pragma unroll 5
            for (int v = 0; v < Vv; v++) {
                ull ya = pack2(yp[v],         yp[SYS + v]);
                ull yb = pack2(yp[2*SYS + v], yp[3*SYS + v]);
                const float* pv = pabase + v*Vv;
                #pragma unroll
                for (int j = 0; j < 5; j++) {
                    ull pj = pack2s(pv[j]);
                    fma2(acc0[j], ya, pj);
                    fma2(acc1[j], yb, pj);
                }
            }
        }

        // epilogue: BN + relu, residual add, relu, store
        float sc0 = sscale[o0],   sh0 = sshift[o0];
        float sc1 = sscale[o0+1], sh1 = sshift[o0+1];
        float sc2 = sscale[o0+2], sh2 = sshift[o0+2];
        float sc3 = sscale[o0+3], sh3 = sshift[o0+3];

        const long long obase = (((long long)n*Oo)*Tt + (t0+tq))*Vv;  // + o*Tt*Vv later
        #pragma unroll
        for (int j = 0; j < 5; j++) {
            int w = w0 + j;
            float2 a = unpack2(acc0[j]);
            float2 bq = unpack2(acc1[j]);
            float z0 = fmaxf(fmaf(a.x,  sc0, sh0), 0.f);
            float z1 = fmaxf(fmaf(a.y,  sc1, sh1), 0.f);
            float z2 = fmaxf(fmaf(bq.x, sc2, sh2), 0.f);
            float z3 = fmaxf(fmaf(bq.y, sc3, sh3), 0.f);
            float r0 = sx[(o0+0)*SXS + tq*Vv + w];
            float r1 = sx[(o0+1)*SXS + tq*Vv + w];
            float r2 = sx[(o0+2)*SXS + tq*Vv + w];
            float r3 = sx[(o0+3)*SXS + tq*Vv + w];
            long long base = (obase + w)*Mm + m;
            const long long ostride = (long long)Tt*Vv*Mm;
            out[base + (o0+0)*ostride] = fmaxf(z0 + r0, 0.f);
            out[base + (o0+1)*ostride] = fmaxf(z1 + r1, 0.f);
            out[base + (o0+2)*ostride] = fmaxf(z2 + r2, 0.f);
            out[base + (o0+3)*ostride] = fmaxf(z3 + r3, 0.f);
        }
    }
}

extern "C" void kernel_launch(void* const* d_in, const int* in_sizes, int n_in,
                              void* d_out, int out_size)
{
    const float* x     = (const float*)d_in[0];
    const float* PA    = (const float*)d_in[1];
    const float* Wc    = (const float*)d_in[2];
    const float* bc    = (const float*)d_in[3];
    const float* gamma = (const float*)d_in[4];
    const float* beta  = (const float*)d_in[5];
    const float* mean  = (const float*)d_in[6];
    const float* var   = (const float*)d_in[7];
    float* out = (float*)d_out;

    const int smem_bytes = SM_FLOATS * (int)sizeof(float);  // ~213.8 KB
    cudaFuncSetAttribute(stgcn_fused_kernel,
                         cudaFuncAttributeMaxDynamicSharedMemorySize, smem_bytes);

    dim3 grid(64 * (Tt / TTile));   // 3200
    stgcn_fused_kernel<<<grid, THREADS, smem_bytes>>>(
        x, PA, Wc, bc, gamma, beta, mean, var, out);
}

// round 3
// speedup vs baseline: 1.0127x; 1.0127x over previous
#include <cuda_runtime.h>
#include <math.h>

// Problem constants
#define Nn 32
#define Cc 64
#define Tt 300
#define Vv 25
#define Mm 2
#define Oo 64
#define Ss 3
#define SO 192          // S*O rows of conv_w
#define TTile 6         // T-tile per block (300 = 50*6)
#define TVC (TTile*Vv)  // 150 columns per tile
#define SXS 152         // padded stride for sx/sy (even -> 8B-aligned pairs)
#define SYS 152
#define SWS 193         // padded stride for transposed W
#define THREADS 480     // 15 warps; tasks per stage == 480 exactly

#define SM_FLOATS (Cc*SXS + SO*SYS + Cc*SWS + Ss*Vv*Vv + SO + Oo + Oo)

typedef unsigned long long ull;

__device__ __forceinline__ ull pack2(float lo, float hi) {
    ull r; asm("mov.b64 %0, {%1,%2};" : "=l"(r) : "f"(lo), "f"(hi)); return r;
}
__device__ __forceinline__ ull pack2s(float v) {
    ull r; asm("mov.b64 %0, {%1,%1};" : "=l"(r) : "f"(v)); return r;
}
__device__ __forceinline__ void fma2(ull& d, ull a, ull b) {
    asm("fma.rn.f32x2 %0, %1, %2, %0;" : "+l"(d) : "l"(a), "l"(b));
}
__device__ __forceinline__ float2 unpack2(ull v) {
    float2 f; asm("mov.b64 {%0,%1}, %2;" : "=f"(f.x), "=f"(f.y) : "l"(v)); return f;
}

__global__ __launch_bounds__(THREADS, 1)
void stgcn_fused_kernel(const float* __restrict__ x,
                        const float* __restrict__ PA,
                        const float* __restrict__ Wc,
                        const float* __restrict__ bc,
                        const float* __restrict__ gamma,
                        const float* __restrict__ beta,
                        const float* __restrict__ mean,
                        const float* __restrict__ var,
                        float* __restrict__ out)
{
    extern __shared__ float sm[];
    float* sx     = sm;                      // 64*152
    float* sy     = sx + Cc*SXS;             // 192*152
    float* sW     = sy + SO*SYS;             // 64*193
    float* sPA    = sW + Cc*SWS;             // 1875
    float* sbias  = sPA + Ss*Vv*Vv;          // 192
    float* sscale = sbias + SO;              // 64
    float* sshift = sscale + Oo;             // 64

    const int tid  = threadIdx.x;
    const int bid  = blockIdx.x;
    const int b    = bid & 63;               // batch index (n*2+m), fastest
    const int tile = bid >> 6;
    const int n    = b >> 1;
    const int m    = b & 1;
    const int t0   = tile * TTile;

    // ---- cooperative loads ----
    for (int i = tid; i < Ss*Vv*Vv; i += THREADS) sPA[i] = PA[i];
    for (int i = tid; i < SO; i += THREADS)       sbias[i] = bc[i];
    if (tid < Oo) {
        float sc = gamma[tid] * rsqrtf(var[tid] + 1e-5f);
        sscale[tid] = sc;
        sshift[tid] = beta[tid] - mean[tid] * sc;
    }
    // W transpose into smem: sW[c][so] = conv_w[so][c]
    for (int i = tid; i < SO*Cc; i += THREADS) {
        int so = i >> 6;
        int c  = i & 63;
        sW[c*SWS + so] = Wc[i];
    }
    // x tile: gather (stride-2 in global due to M-last layout)
    for (int i = tid; i < Cc*TVC; i += THREADS) {
        int c  = i / TVC;
        int tv = i - c*TVC;
        int t  = tv / Vv;
        int v  = tv - t*Vv;
        sx[c*SXS + tv] = x[ (((n*Cc + c)*Tt + (t0+t))*Vv + v)*Mm + m ];
    }
    __syncthreads();

    // ---- Stage A: conv GEMM  y[so][tv] = bias[so] + sum_c W[so][c]*x[c][tv]
    // 192x150 outputs, reg tile 6(so) x 10(tv as 5 f32x2 pairs); 32x15 = 480 tasks
    {
        const int sog = tid / 15;          // 0..31
        const int tvg = tid - sog*15;      // 0..14
        const int so0 = sog*6;
        const int tv0 = tvg*10;            // even -> 8B aligned pairs

        ull acc[6][5];
        #pragma unroll
        for (int i = 0; i < 6; i++) {
            ull bb = pack2s(sbias[so0+i]);
            #pragma unroll
            for (int j = 0; j < 5; j++) acc[i][j] = bb;
        }

        #pragma unroll 2
        for (int c = 0; c < Cc; c++) {
            const float* xrow = sx + c*SXS + tv0;
            ull xv[5];
            #pragma unroll
            for (int j = 0; j < 5; j++)
                xv[j] = *reinterpret_cast<const ull*>(xrow + 2*j);
            const float* wrow = sW + c*SWS + so0;
            #pragma unroll
            for (int i = 0; i < 6; i++) {
                ull wv = pack2s(wrow[i]);
                #pragma unroll
                for (int j = 0; j < 5; j++) fma2(acc[i][j], wv, xv[j]);
            }
        }

        #pragma unroll
        for (int i = 0; i < 6; i++) {
            float* yrow = sy + (so0+i)*SYS + tv0;
            #pragma unroll
            for (int j = 0; j < 5; j++)
                *reinterpret_cast<ull*>(yrow + 2*j) = acc[i][j];
        }
    }
    __syncthreads();

    // ---- Stage B: adjacency + BN + relu + residual + relu + store
    // z[o][t][w] = sum_s sum_v PA[s][v][w] * y[s*64+o][t*25+v]
    // reg tile 4(o as 2 f32x2 pairs) x 5(w); 16(og)*6(t)*5(wg) = 480 tasks
    {
        const int wg  = tid % 5;
        const int tq  = (tid/5) % 6;
        const int og  = tid / 30;          // 0..15
        const int o0  = og*4;
        const int w0  = wg*5;

        ull acc0[5], acc1[5];
        #pragma unroll
        for (int j = 0; j < 5; j++) { acc0[j] = 0ull; acc1[j] = 0ull; }

        #pragma unroll
        for (int s = 0; s < Ss; s++) {
            const float* pabase = sPA + s*(Vv*Vv) + w0;
            const float* yp     = sy + (s*Oo + o0)*SYS + tq*Vv;
            #pragma unroll 5
            for (int v = 0; v < Vv; v++) {
                ull ya = pack2(yp[v],         yp[SYS + v]);
                ull yb = pack2(yp[2*SYS + v], yp[3*SYS + v]);
                const float* pv = pabase + v*Vv;
                #pragma unroll
                for (int j = 0; j < 5; j++) {
                    ull pj = pack2s(pv[j]);
                    fma2(acc0[j], ya, pj);
                    fma2(acc1[j], yb, pj);
                }
            }
        }

        // epilogue: BN + relu, residual add, relu, store
        float sc0 = sscale[o0],   sh0 = sshift[o0];
        float sc1 = sscale[o0+1], sh1 = sshift[o0+1];
        float sc2 = sscale[o0+2], sh2 = sshift[o0+2];
        float sc3 = sscale[o0+3], sh3 = sshift[o0+3];

        const long long obase = (((long long)n*Oo)*Tt + (t0+tq))*Vv;  // + o*Tt*Vv later
        #pragma unroll
        for (int j = 0; j < 5; j++) {
            int w = w0 + j;
            float2 a = unpack2(acc0[j]);
            float2 bq = unpack2(acc1[j]);
            float z0 = fmaxf(fmaf(a.x,  sc0, sh0), 0.f);
            float z1 = fmaxf(fmaf(a.y,  sc1, sh1), 0.f);
            float z2 = fmaxf(fmaf(bq.x, sc2, sh2), 0.f);
            float z3 = fmaxf(fmaf(bq.y, sc3, sh3), 0.f);
            float r0 = sx[(o0+0)*SXS + tq*Vv + w];
            float r1 = sx[(o0+1)*SXS + tq*Vv + w];
            float r2 = sx[(o0+2)*SXS + tq*Vv + w];
            float r3 = sx[(o0+3)*SXS + tq*Vv + w];
            long long base = (obase + w)*Mm + m;
            const long long ostride = (long long)Tt*Vv*Mm;
            out[base + (o0+0)*ostride] = fmaxf(z0 + r0, 0.f);
            out[base + (o0+1)*ostride] = fmaxf(z1 + r1, 0.f);
            out[base + (o0+2)*ostride] = fmaxf(z2 + r2, 0.f);
            out[base + (o0+3)*ostride] = fmaxf(z3 + r3, 0.f);
        }
    }
}

extern "C" void kernel_launch(void* const* d_in, const int* in_sizes, int n_in,
                              void* d_out, int out_size)
{
    const float* x     = (const float*)d_in[0];
    const float* PA    = (const float*)d_in[1];
    const float* Wc    = (const float*)d_in[2];
    const float* bc    = (const float*)d_in[3];
    const float* gamma = (const float*)d_in[4];
    const float* beta  = (const float*)d_in[5];
    const float* mean  = (const float*)d_in[6];
    const float* var   = (const float*)d_in[7];
    float* out = (float*)d_out;

    const int smem_bytes = SM_FLOATS * (int)sizeof(float);  // ~213.8 KB
    cudaFuncSetAttribute(stgcn_fused_kernel,
                         cudaFuncAttributeMaxDynamicSharedMemorySize, smem_bytes);

    dim3 grid(64 * (Tt / TTile));   // 3200
    stgcn_fused_kernel<<<grid, THREADS, smem_bytes>>>(
        x, PA, Wc, bc, gamma, beta, mean, var, out);
}